// round 11
// baseline (speedup 1.0000x reference)
#include <cuda_runtime.h>
#include <cuda_bf16.h>
#include <math.h>

// Problem constants (fixed by reference setup_inputs)
#define BB 8
#define TT 16
#define CC 64
#define NN 4096          // H*W
#define KSEL 2048        // keep_k = N*(1-0.5)

#define CHUNKB 2         // batches per chunk
#define CGROUPS 4        // c-split: full thread count per chunk
#define CPER 16          // channels per group

typedef unsigned long long ull;

// Scratch (device globals — no allocation allowed)
__device__ float g_partial4[BB * TT * CGROUPS * NN];  // sum(x^2) per (b,t,cg,n)
__device__ unsigned g_maskbits[BB * (NN / 32)];       // 1 bit per (b,n)

__device__ __forceinline__ ull warp_sum_u64(ull v) {
#pragma unroll
    for (int d = 16; d; d >>= 1) v += __shfl_xor_sync(0xffffffffu, v, d);
    return v;
}

// ---------------------------------------------------------------------------
// K1: pure chunk scoring. 2048 blocks x 256 threads per chunk = 524288
// threads (same aggregate MLP/shape as the 5.7 TB/s monolithic k_partial).
// Each thread: 16 loads at stride NN, one partial write. NO tail work.
// ---------------------------------------------------------------------------
__global__ void __launch_bounds__(256) k1_score(const float* __restrict__ x,
                                                int chunk) {
    const int idx = blockIdx.x * 256 + threadIdx.x;   // [0, 524288)
    const int n   = idx & (NN - 1);
    const int cg  = (idx >> 12) & (CGROUPS - 1);
    const int btl = idx >> 14;                         // 0..31
    const int bt  = chunk * (CHUNKB * TT) + btl;       // global b*TT + t

    const float* p = x + (size_t)bt * CC * NN + (size_t)(cg * CPER) * NN + n;
    float acc = 0.0f;
#pragma unroll
    for (int c = 0; c < CPER; ++c) {
        float v = p[(size_t)c * NN];
        acc += v * v;
    }
    g_partial4[((size_t)bt * CGROUPS + cg) * NN + n] = acc;
}

// ---------------------------------------------------------------------------
// S: per-batch exact top-K -> mask bits (R9-verified body, own launch).
// 2 blocks x 1024 threads per chunk; block b' handles batch chunk*2+b'.
// Partials are L2-hot (written by the K1 immediately preceding).
// ---------------------------------------------------------------------------
__global__ void __launch_bounds__(1024, 1) k_select(int chunk) {
    __shared__ ull s_red64[2][32];
    __shared__ unsigned s_u32[66];
    __shared__ unsigned s_mask[NN / 32];
    __shared__ int s_scan[32];
    __shared__ int s_int[1];

    const int b    = chunk * CHUNKB + blockIdx.x;
    const int j    = threadIdx.x;              // 0..1023
    const int lane = j & 31;
    const int wid  = j >> 5;

    // --- scores: 4 n per thread; per t: sum 4 group partials, sqrt, accum ---
    const float4* part = (const float4*)g_partial4;
    float s0 = 0.f, s1 = 0.f, s2 = 0.f, s3 = 0.f;
#pragma unroll
    for (int t = 0; t < TT; ++t) {
        size_t base = (size_t)(b * TT + t) * CGROUPS * (NN / 4);
        float4 p0 = part[base + 0 * (NN / 4) + j];
        float4 p1 = part[base + 1 * (NN / 4) + j];
        float4 p2 = part[base + 2 * (NN / 4) + j];
        float4 p3 = part[base + 3 * (NN / 4) + j];
        s0 += sqrtf(p0.x + p1.x + p2.x + p3.x);
        s1 += sqrtf(p0.y + p1.y + p2.y + p3.y);
        s2 += sqrtf(p0.z + p1.z + p2.z + p3.z);
        s3 += sqrtf(p0.w + p1.w + p2.w + p3.w);
    }
    const float inv = 1.0f / (float)TT;
    unsigned u0 = __float_as_uint(s0 * inv);
    unsigned u1 = __float_as_uint(s1 * inv);
    unsigned u2 = __float_as_uint(s2 * inv);
    unsigned u3 = __float_as_uint(s3 * inv);

    if (j < NN / 32) s_mask[j] = 0u;

    // --- block OR / AND of all score bits ---
    unsigned ov = u0 | u1 | u2 | u3;
    unsigned av = u0 & u1 & u2 & u3;
#pragma unroll
    for (int d = 16; d; d >>= 1) {
        ov |= __shfl_xor_sync(0xffffffffu, ov, d);
        av &= __shfl_xor_sync(0xffffffffu, av, d);
    }
    if (lane == 0) { s_u32[wid] = ov; s_u32[32 + wid] = av; }
    __syncthreads();
    {
        unsigned o2 = s_u32[lane], a2 = s_u32[32 + lane];
#pragma unroll
        for (int d = 16; d; d >>= 1) {
            o2 |= __shfl_xor_sync(0xffffffffu, o2, d);
            a2 &= __shfl_xor_sync(0xffffffffu, a2, d);
        }
        if (j == 0) { s_u32[64] = o2; s_u32[65] = a2; }
    }
    __syncthreads();
    const unsigned orv  = s_u32[64];
    const unsigned andv = s_u32[65];
    const unsigned diff = orv ^ andv;

    // --- 2-bit radix select: largest thr with count(u >= thr) >= KSEL ---
    unsigned thr = 0u;
    int par = 0;
#pragma unroll
    for (int p = 15; p >= 0; --p) {
        unsigned m2 = 3u << (2 * p);
        if ((diff & m2) == 0u) {               // both bits uniform across block
            thr |= (andv & m2);
            continue;
        }
        unsigned c1 = thr | (1u << (2 * p));
        unsigned c2 = thr | (2u << (2 * p));
        unsigned c3 = thr | (3u << (2 * p));
        int n1 = (u0 >= c1) + (u1 >= c1) + (u2 >= c1) + (u3 >= c1);
        int n2 = (u0 >= c2) + (u1 >= c2) + (u2 >= c2) + (u3 >= c2);
        int n3 = (u0 >= c3) + (u1 >= c3) + (u2 >= c3) + (u3 >= c3);
        ull pk = (ull)n1 | ((ull)n2 << 20) | ((ull)n3 << 40);
        pk = warp_sum_u64(pk);
        if (lane == 0) s_red64[par][wid] = pk;
        __syncthreads();
        ull tot = warp_sum_u64(s_red64[par][lane]);
        int N1 = (int)(tot & 0xFFFFFull);
        int N2 = (int)((tot >> 20) & 0xFFFFFull);
        int N3 = (int)((tot >> 40) & 0xFFFFFull);
        if      (N3 >= KSEL) thr = c3;
        else if (N2 >= KSEL) thr = c2;
        else if (N1 >= KSEL) thr = c1;
        par ^= 1;
    }
    __syncthreads();   // protect s_red64 before reuse below

    // --- strictly-greater count (ties admitted by lowest index) ---
    {
        ull pk = (ull)((u0 > thr) + (u1 > thr) + (u2 > thr) + (u3 > thr));
        pk = warp_sum_u64(pk);
        if (lane == 0) s_red64[0][wid] = pk;
        __syncthreads();
        ull tot = warp_sum_u64(s_red64[0][lane]);
        if (j == 0) s_int[0] = (int)tot;
        __syncthreads();
    }
    int need = KSEL - s_int[0];

    // --- exclusive scan over threads of per-thread equal-count ---
    int e = (u0 == thr) + (u1 == thr) + (u2 == thr) + (u3 == thr);
    int v = e;
#pragma unroll
    for (int d = 1; d < 32; d <<= 1) {
        int t = __shfl_up_sync(0xffffffffu, v, d);
        if (lane >= d) v += t;
    }
    if (lane == 31) s_scan[wid] = v;
    __syncthreads();
    if (wid == 0) {
        int w = s_scan[lane];
#pragma unroll
        for (int d = 1; d < 32; d <<= 1) {
            int t = __shfl_up_sync(0xffffffffu, w, d);
            if (lane >= d) w += t;
        }
        s_scan[lane] = w;
    }
    __syncthreads();
    int excl = v - e + (wid ? s_scan[wid - 1] : 0);

    // --- mask nibble for n = 4j..4j+3 ---
    unsigned nib = 0;
    int r = excl;
    unsigned uu[4] = {u0, u1, u2, u3};
#pragma unroll
    for (int i = 0; i < 4; ++i) {
        if (uu[i] > thr) {
            nib |= 1u << i;
        } else if (uu[i] == thr) {
            if (r < need) nib |= 1u << i;
            ++r;
        }
    }
    atomicOr(&s_mask[j >> 3], nib << ((j & 7) * 4));
    __syncthreads();
    if (j < NN / 32) g_maskbits[b * (NN / 32) + j] = s_mask[j];
}

// ---------------------------------------------------------------------------
// M: masked copy for one chunk (R9-verified, ~8.4us measured there).
// Reads hit x[chunk]'s L2 residue from K1(chunk).
// ---------------------------------------------------------------------------
__global__ void __launch_bounds__(256) k_mask(const float4* __restrict__ x4,
                                              float4* __restrict__ o4,
                                              int chunk) {
    unsigned i = (unsigned)chunk * (CHUNKB * TT * CC * NN / 4)
               + blockIdx.x * 256 + threadIdx.x;
    int n4 = i & ((NN / 4) - 1);
    int b  = i >> 20;                        // 2^20 float4 per batch
    int n  = n4 << 2;
    unsigned mword = g_maskbits[(b << 7) + (n >> 5)];
    unsigned bits  = mword >> (n & 31);
    float4 v = __ldcs(&x4[(size_t)i]);
    v.x = (bits & 1u) ? v.x : 0.0f;
    v.y = (bits & 2u) ? v.y : 0.0f;
    v.z = (bits & 4u) ? v.z : 0.0f;
    v.w = (bits & 8u) ? v.w : 0.0f;
    __stcs(&o4[(size_t)i], v);
}

// ---------------------------------------------------------------------------
extern "C" void kernel_launch(void* const* d_in, const int* in_sizes, int n_in,
                              void* d_out, int out_size) {
    const float* x = (const float*)d_in[0];
    float* out = (float*)d_out;

    const int K1_GRID = CHUNKB * TT * CGROUPS * NN / 256;  // 2048 blocks
    const int M_GRID  = CHUNKB * TT * CC * NN / 4 / 256;   // 8192 blocks

    // Pipeline: S(c) right after K1(c) (partials L2-hot); M(c) one chunk
    // behind K1 so x[c] is still L2-resident when re-read.
    k1_score<<<K1_GRID, 256>>>(x, 0);
    k_select<<<CHUNKB, 1024>>>(0);
    k1_score<<<K1_GRID, 256>>>(x, 1);
    k_select<<<CHUNKB, 1024>>>(1);
    k_mask<<<M_GRID, 256>>>((const float4*)x, (float4*)out, 0);
    k1_score<<<K1_GRID, 256>>>(x, 2);
    k_select<<<CHUNKB, 1024>>>(2);
    k_mask<<<M_GRID, 256>>>((const float4*)x, (float4*)out, 1);
    k1_score<<<K1_GRID, 256>>>(x, 3);
    k_select<<<CHUNKB, 1024>>>(3);
    k_mask<<<M_GRID, 256>>>((const float4*)x, (float4*)out, 2);
    k_mask<<<M_GRID, 256>>>((const float4*)x, (float4*)out, 3);
}

// round 12
// speedup vs baseline: 1.2116x; 1.2116x over previous
#include <cuda_runtime.h>
#include <cuda_bf16.h>
#include <math.h>

// Problem constants (fixed by reference setup_inputs)
#define BB 8
#define TT 16
#define CC 64
#define NN 4096          // H*W
#define KSEL 2048        // keep_k = N*(1-0.5)

#define CHUNKB 2         // batches per chunk
#define CGROUPS 4        // c-groups combined in-block
#define CPER 16          // channels per group

typedef unsigned long long ull;

// Scratch (device globals — no allocation allowed)
__device__ float g_sq[BB * TT * NN];             // sqrt(sum_c x^2) per (b,t,n), 2 MB
__device__ unsigned g_maskbits[BB * (NN / 32)];  // 1 bit per (b,n)

__device__ __forceinline__ ull warp_sum_u64(ull v) {
#pragma unroll
    for (int d = 16; d; d >>= 1) v += __shfl_xor_sync(0xffffffffu, v, d);
    return v;
}

// ---------------------------------------------------------------------------
// K1': chunk scoring with in-block c-group combine. 2048 blocks x 256 thr
// per chunk (524288 threads -> full streaming MLP). Block = (bt, 64-n range);
// tid = cg*64 + nl. Warp covers 32 consecutive n at fixed cg: coalesced 128B
// loads. Group sums meet in shared memory; 64 threads do the sqrt + 256B
// contiguous store. Partials never touch DRAM/L2 as 4-group intermediates.
// ---------------------------------------------------------------------------
__global__ void __launch_bounds__(256) k1_score(const float* __restrict__ x,
                                                int chunk) {
    __shared__ float s_part[CGROUPS * 64];

    const int tid = threadIdx.x;
    const int cg  = tid >> 6;                  // 0..3
    const int nl  = tid & 63;                  // 0..63
    const int btl = blockIdx.x >> 6;           // 0..31
    const int nb  = blockIdx.x & 63;           // 0..63
    const int bt  = chunk * (CHUNKB * TT) + btl;
    const int n   = nb * 64 + nl;

    const float* p = x + (size_t)bt * CC * NN + (size_t)(cg * CPER) * NN + n;
    float acc = 0.0f;
#pragma unroll
    for (int c = 0; c < CPER; ++c) {
        float v = p[(size_t)c * NN];
        acc += v * v;
    }
    s_part[cg * 64 + nl] = acc;
    __syncthreads();

    if (tid < 64) {
        float total = s_part[tid] + s_part[64 + tid]
                    + s_part[128 + tid] + s_part[192 + tid];
        g_sq[(size_t)bt * NN + nb * 64 + tid] = sqrtf(total);
    }
}

// ---------------------------------------------------------------------------
// S: per-batch exact top-K -> mask bits (R5-form: reads ready sqrt-partials,
// 4 n per thread, t-loop, 2-bit radix). 2 blocks x 1024 threads per chunk.
// Data is L2-hot (written by the K1' immediately preceding).
// ---------------------------------------------------------------------------
__global__ void __launch_bounds__(1024, 1) k_select(int chunk) {
    __shared__ ull s_red64[2][32];
    __shared__ unsigned s_u32[66];
    __shared__ unsigned s_mask[NN / 32];
    __shared__ int s_scan[32];
    __shared__ int s_int[1];

    const int b    = chunk * CHUNKB + blockIdx.x;
    const int j    = threadIdx.x;              // 0..1023
    const int lane = j & 31;
    const int wid  = j >> 5;

    // --- scores: 4 per thread, sequential over t (same order as verified) ---
    const float4* part = (const float4*)g_sq;
    float s0 = 0.f, s1 = 0.f, s2 = 0.f, s3 = 0.f;
#pragma unroll
    for (int t = 0; t < TT; ++t) {
        float4 f = part[(size_t)(b * TT + t) * (NN / 4) + j];
        s0 += f.x; s1 += f.y; s2 += f.z; s3 += f.w;
    }
    const float inv = 1.0f / (float)TT;
    unsigned u0 = __float_as_uint(s0 * inv);
    unsigned u1 = __float_as_uint(s1 * inv);
    unsigned u2 = __float_as_uint(s2 * inv);
    unsigned u3 = __float_as_uint(s3 * inv);

    if (j < NN / 32) s_mask[j] = 0u;

    // --- block OR / AND of all score bits ---
    unsigned ov = u0 | u1 | u2 | u3;
    unsigned av = u0 & u1 & u2 & u3;
#pragma unroll
    for (int d = 16; d; d >>= 1) {
        ov |= __shfl_xor_sync(0xffffffffu, ov, d);
        av &= __shfl_xor_sync(0xffffffffu, av, d);
    }
    if (lane == 0) { s_u32[wid] = ov; s_u32[32 + wid] = av; }
    __syncthreads();
    {
        unsigned o2 = s_u32[lane], a2 = s_u32[32 + lane];
#pragma unroll
        for (int d = 16; d; d >>= 1) {
            o2 |= __shfl_xor_sync(0xffffffffu, o2, d);
            a2 &= __shfl_xor_sync(0xffffffffu, a2, d);
        }
        if (j == 0) { s_u32[64] = o2; s_u32[65] = a2; }
    }
    __syncthreads();
    const unsigned orv  = s_u32[64];
    const unsigned andv = s_u32[65];
    const unsigned diff = orv ^ andv;

    // --- 2-bit radix select: largest thr with count(u >= thr) >= KSEL ---
    unsigned thr = 0u;
    int par = 0;
#pragma unroll
    for (int p = 15; p >= 0; --p) {
        unsigned m2 = 3u << (2 * p);
        if ((diff & m2) == 0u) {               // both bits uniform across block
            thr |= (andv & m2);
            continue;
        }
        unsigned c1 = thr | (1u << (2 * p));
        unsigned c2 = thr | (2u << (2 * p));
        unsigned c3 = thr | (3u << (2 * p));
        int n1 = (u0 >= c1) + (u1 >= c1) + (u2 >= c1) + (u3 >= c1);
        int n2 = (u0 >= c2) + (u1 >= c2) + (u2 >= c2) + (u3 >= c2);
        int n3 = (u0 >= c3) + (u1 >= c3) + (u2 >= c3) + (u3 >= c3);
        ull pk = (ull)n1 | ((ull)n2 << 20) | ((ull)n3 << 40);
        pk = warp_sum_u64(pk);
        if (lane == 0) s_red64[par][wid] = pk;
        __syncthreads();
        ull tot = warp_sum_u64(s_red64[par][lane]);
        int N1 = (int)(tot & 0xFFFFFull);
        int N2 = (int)((tot >> 20) & 0xFFFFFull);
        int N3 = (int)((tot >> 40) & 0xFFFFFull);
        if      (N3 >= KSEL) thr = c3;
        else if (N2 >= KSEL) thr = c2;
        else if (N1 >= KSEL) thr = c1;
        par ^= 1;
    }
    __syncthreads();   // protect s_red64 before reuse below

    // --- strictly-greater count (ties admitted by lowest index) ---
    {
        ull pk = (ull)((u0 > thr) + (u1 > thr) + (u2 > thr) + (u3 > thr));
        pk = warp_sum_u64(pk);
        if (lane == 0) s_red64[0][wid] = pk;
        __syncthreads();
        ull tot = warp_sum_u64(s_red64[0][lane]);
        if (j == 0) s_int[0] = (int)tot;
        __syncthreads();
    }
    int need = KSEL - s_int[0];

    // --- exclusive scan over threads of per-thread equal-count ---
    int e = (u0 == thr) + (u1 == thr) + (u2 == thr) + (u3 == thr);
    int v = e;
#pragma unroll
    for (int d = 1; d < 32; d <<= 1) {
        int t = __shfl_up_sync(0xffffffffu, v, d);
        if (lane >= d) v += t;
    }
    if (lane == 31) s_scan[wid] = v;
    __syncthreads();
    if (wid == 0) {
        int w = s_scan[lane];
#pragma unroll
        for (int d = 1; d < 32; d <<= 1) {
            int t = __shfl_up_sync(0xffffffffu, w, d);
            if (lane >= d) w += t;
        }
        s_scan[lane] = w;
    }
    __syncthreads();
    int excl = v - e + (wid ? s_scan[wid - 1] : 0);

    // --- mask nibble for n = 4j..4j+3 ---
    unsigned nib = 0;
    int r = excl;
    unsigned uu[4] = {u0, u1, u2, u3};
#pragma unroll
    for (int i = 0; i < 4; ++i) {
        if (uu[i] > thr) {
            nib |= 1u << i;
        } else if (uu[i] == thr) {
            if (r < need) nib |= 1u << i;
            ++r;
        }
    }
    atomicOr(&s_mask[j >> 3], nib << ((j & 7) * 4));
    __syncthreads();
    if (j < NN / 32) g_maskbits[b * (NN / 32) + j] = s_mask[j];
}

// ---------------------------------------------------------------------------
// M: masked copy for one chunk (verified; ~5us with L2-hot reads).
// ---------------------------------------------------------------------------
__global__ void __launch_bounds__(256) k_mask(const float4* __restrict__ x4,
                                              float4* __restrict__ o4,
                                              int chunk) {
    unsigned i = (unsigned)chunk * (CHUNKB * TT * CC * NN / 4)
               + blockIdx.x * 256 + threadIdx.x;
    int n4 = i & ((NN / 4) - 1);
    int b  = i >> 20;                        // 2^20 float4 per batch
    int n  = n4 << 2;
    unsigned mword = g_maskbits[(b << 7) + (n >> 5)];
    unsigned bits  = mword >> (n & 31);
    float4 v = __ldcs(&x4[(size_t)i]);
    v.x = (bits & 1u) ? v.x : 0.0f;
    v.y = (bits & 2u) ? v.y : 0.0f;
    v.z = (bits & 4u) ? v.z : 0.0f;
    v.w = (bits & 8u) ? v.w : 0.0f;
    __stcs(&o4[(size_t)i], v);
}

// ---------------------------------------------------------------------------
extern "C" void kernel_launch(void* const* d_in, const int* in_sizes, int n_in,
                              void* d_out, int out_size) {
    const float* x = (const float*)d_in[0];
    float* out = (float*)d_out;

    const int K1_GRID = CHUNKB * TT * 64;                   // 2048 blocks
    const int M_GRID  = CHUNKB * TT * CC * NN / 4 / 256;    // 8192 blocks

    // Pipeline: S(c) right after K1(c) (sqrt-partials L2-hot); M(c) one chunk
    // behind K1 so x[c] is still L2-resident when re-read.
    k1_score<<<K1_GRID, 256>>>(x, 0);
    k_select<<<CHUNKB, 1024>>>(0);
    k1_score<<<K1_GRID, 256>>>(x, 1);
    k_select<<<CHUNKB, 1024>>>(1);
    k_mask<<<M_GRID, 256>>>((const float4*)x, (float4*)out, 0);
    k1_score<<<K1_GRID, 256>>>(x, 2);
    k_select<<<CHUNKB, 1024>>>(2);
    k_mask<<<M_GRID, 256>>>((const float4*)x, (float4*)out, 1);
    k1_score<<<K1_GRID, 256>>>(x, 3);
    k_select<<<CHUNKB, 1024>>>(3);
    k_mask<<<M_GRID, 256>>>((const float4*)x, (float4*)out, 2);
    k_mask<<<M_GRID, 256>>>((const float4*)x, (float4*)out, 3);
}

// round 13
// speedup vs baseline: 1.4172x; 1.1697x over previous
#include <cuda_runtime.h>
#include <cuda_bf16.h>
#include <math.h>

// Problem constants (fixed by reference setup_inputs)
#define BB 8
#define TT 16
#define CC 64
#define NN 4096          // H*W
#define KSEL 2048        // keep_k = N*(1-0.5)

#define CHUNKB 2         // batches per chunk
#define CGROUPS 4        // c-groups combined in-block
#define CPER 16          // channels per group
#define FULL 0xffffffffu

// Scratch (device globals — no allocation allowed)
__device__ float g_sq[BB * TT * NN];             // sqrt(sum_c x^2) per (b,t,n), 2 MB
__device__ unsigned g_maskbits[BB * (NN / 32)];  // 1 bit per (b,n)

// ---------------------------------------------------------------------------
// K1' (R12 form): chunk scoring with in-block c-group combine. 2048 blocks x
// 256 threads per chunk; warp = 32 consecutive n at fixed cg (coalesced).
// Group sums combine in shared memory; sqrt applied here (spread over all SMs).
// ---------------------------------------------------------------------------
__global__ void __launch_bounds__(256) k1_score(const float* __restrict__ x,
                                                int chunk) {
    __shared__ float s_part[CGROUPS * 64];

    const int tid = threadIdx.x;
    const int cg  = tid >> 6;                  // 0..3
    const int nl  = tid & 63;                  // 0..63
    const int btl = blockIdx.x >> 6;           // 0..31
    const int nb  = blockIdx.x & 63;           // 0..63
    const int bt  = chunk * (CHUNKB * TT) + btl;
    const int n   = nb * 64 + nl;

    const float* p = x + (size_t)bt * CC * NN + (size_t)(cg * CPER) * NN + n;
    float acc = 0.0f;
#pragma unroll
    for (int c = 0; c < CPER; ++c) {
        float v = p[(size_t)c * NN];
        acc += v * v;
    }
    s_part[cg * 64 + nl] = acc;
    __syncthreads();

    if (tid < 64) {
        float total = s_part[tid] + s_part[64 + tid]
                    + s_part[128 + tid] + s_part[192 + tid];
        g_sq[(size_t)bt * NN + nb * 64 + tid] = sqrtf(total);
    }
}

// ---------------------------------------------------------------------------
// S: per-batch exact top-K -> mask bits. Same selection semantics as the
// verified R5/R12 body; all block reductions rewritten with single-instruction
// REDUX (__reduce_*_sync) + one smem hop, double-buffered (1 bar/iteration).
// ---------------------------------------------------------------------------
__global__ void __launch_bounds__(1024, 1) k_select(int chunk) {
    __shared__ int s_c1[2][32], s_c2[2][32], s_c3[2][32];  // per-warp counts
    __shared__ unsigned s_or[32], s_and[32];
    __shared__ unsigned s_mask[NN / 32];
    __shared__ int s_scan[32];

    const int b    = chunk * CHUNKB + blockIdx.x;
    const int j    = threadIdx.x;              // 0..1023
    const int lane = j & 31;
    const int wid  = j >> 5;

    // --- scores: 4 per thread, sequential over t (verified order) ---
    const float4* part = (const float4*)g_sq;
    float s0 = 0.f, s1 = 0.f, s2 = 0.f, s3 = 0.f;
#pragma unroll
    for (int t = 0; t < TT; ++t) {
        float4 f = part[(size_t)(b * TT + t) * (NN / 4) + j];
        s0 += f.x; s1 += f.y; s2 += f.z; s3 += f.w;
    }
    const float inv = 1.0f / (float)TT;
    unsigned u0 = __float_as_uint(s0 * inv);
    unsigned u1 = __float_as_uint(s1 * inv);
    unsigned u2 = __float_as_uint(s2 * inv);
    unsigned u3 = __float_as_uint(s3 * inv);

    if (j < NN / 32) s_mask[j] = 0u;

    // --- block OR / AND of all score bits (REDUX x2 levels) ---
    {
        unsigned ow = __reduce_or_sync(FULL, u0 | u1 | u2 | u3);
        unsigned aw = __reduce_and_sync(FULL, u0 & u1 & u2 & u3);
        if (lane == 0) { s_or[wid] = ow; s_and[wid] = aw; }
    }
    __syncthreads();
    const unsigned orv  = __reduce_or_sync(FULL, s_or[lane]);
    const unsigned andv = __reduce_and_sync(FULL, s_and[lane]);
    const unsigned diff = orv ^ andv;

    // --- 2-bit radix select: largest thr with count(u >= thr) >= KSEL ---
    unsigned thr = 0u;
    int par = 0;
#pragma unroll
    for (int p = 15; p >= 0; --p) {
        unsigned m2 = 3u << (2 * p);
        if ((diff & m2) == 0u) {               // both bits uniform across block
            thr |= (andv & m2);
            continue;
        }
        unsigned c1 = thr | (1u << (2 * p));
        unsigned c2 = thr | (2u << (2 * p));
        unsigned c3 = thr | (3u << (2 * p));
        int n1 = (u0 >= c1) + (u1 >= c1) + (u2 >= c1) + (u3 >= c1);
        int n2 = (u0 >= c2) + (u1 >= c2) + (u2 >= c2) + (u3 >= c2);
        int n3 = (u0 >= c3) + (u1 >= c3) + (u2 >= c3) + (u3 >= c3);
        n1 = __reduce_add_sync(FULL, n1);
        n2 = __reduce_add_sync(FULL, n2);
        n3 = __reduce_add_sync(FULL, n3);
        if (lane == 0) { s_c1[par][wid] = n1; s_c2[par][wid] = n2; s_c3[par][wid] = n3; }
        __syncthreads();
        // every warp redundantly reduces the 32 per-warp counts (no 2nd bar;
        // double buffering makes next iteration's overwrite safe)
        int N1 = __reduce_add_sync(FULL, s_c1[par][lane]);
        int N2 = __reduce_add_sync(FULL, s_c2[par][lane]);
        int N3 = __reduce_add_sync(FULL, s_c3[par][lane]);
        if      (N3 >= KSEL) thr = c3;
        else if (N2 >= KSEL) thr = c2;
        else if (N1 >= KSEL) thr = c1;
        par ^= 1;
    }
    __syncthreads();   // protect s_c* before reuse below

    // --- strictly-greater count (ties admitted by lowest index) ---
    int n_greater;
    {
        int gt = (u0 > thr) + (u1 > thr) + (u2 > thr) + (u3 > thr);
        gt = __reduce_add_sync(FULL, gt);
        if (lane == 0) s_c1[0][wid] = gt;
        __syncthreads();
        n_greater = __reduce_add_sync(FULL, s_c1[0][lane]);
    }
    const int need = KSEL - n_greater;

    // --- exclusive scan over threads of per-thread equal-count ---
    int e = (u0 == thr) + (u1 == thr) + (u2 == thr) + (u3 == thr);
    int v = e;
#pragma unroll
    for (int d = 1; d < 32; d <<= 1) {
        int t = __shfl_up_sync(FULL, v, d);
        if (lane >= d) v += t;
    }
    if (lane == 31) s_scan[wid] = v;
    __syncthreads();
    if (wid == 0) {
        int w = s_scan[lane];
#pragma unroll
        for (int d = 1; d < 32; d <<= 1) {
            int t = __shfl_up_sync(FULL, w, d);
            if (lane >= d) w += t;
        }
        s_scan[lane] = w;
    }
    __syncthreads();
    int excl = v - e + (wid ? s_scan[wid - 1] : 0);

    // --- mask nibble for n = 4j..4j+3 ---
    unsigned nib = 0;
    int r = excl;
    unsigned uu[4] = {u0, u1, u2, u3};
#pragma unroll
    for (int i = 0; i < 4; ++i) {
        if (uu[i] > thr) {
            nib |= 1u << i;
        } else if (uu[i] == thr) {
            if (r < need) nib |= 1u << i;
            ++r;
        }
    }
    atomicOr(&s_mask[j >> 3], nib << ((j & 7) * 4));
    __syncthreads();
    if (j < NN / 32) g_maskbits[b * (NN / 32) + j] = s_mask[j];
}

// ---------------------------------------------------------------------------
// M: masked copy for one chunk (verified; ~5.5us = 33.5MB write floor).
// Reads hit x[chunk]'s L2 residue from K1(chunk).
// ---------------------------------------------------------------------------
__global__ void __launch_bounds__(256) k_mask(const float4* __restrict__ x4,
                                              float4* __restrict__ o4,
                                              int chunk) {
    unsigned i = (unsigned)chunk * (CHUNKB * TT * CC * NN / 4)
               + blockIdx.x * 256 + threadIdx.x;
    int n4 = i & ((NN / 4) - 1);
    int b  = i >> 20;                        // 2^20 float4 per batch
    int n  = n4 << 2;
    unsigned mword = g_maskbits[(b << 7) + (n >> 5)];
    unsigned bits  = mword >> (n & 31);
    float4 v = __ldcs(&x4[(size_t)i]);
    v.x = (bits & 1u) ? v.x : 0.0f;
    v.y = (bits & 2u) ? v.y : 0.0f;
    v.z = (bits & 4u) ? v.z : 0.0f;
    v.w = (bits & 8u) ? v.w : 0.0f;
    __stcs(&o4[(size_t)i], v);
}

// ---------------------------------------------------------------------------
extern "C" void kernel_launch(void* const* d_in, const int* in_sizes, int n_in,
                              void* d_out, int out_size) {
    const float* x = (const float*)d_in[0];
    float* out = (float*)d_out;

    const int K1_GRID = CHUNKB * TT * 64;                   // 2048 blocks
    const int M_GRID  = CHUNKB * TT * CC * NN / 4 / 256;    // 8192 blocks

    // Pipeline: S(c) right after K1(c) (sqrt-partials L2-hot); M(c) one chunk
    // behind K1 so x[c] is still L2-resident when re-read.
    k1_score<<<K1_GRID, 256>>>(x, 0);
    k_select<<<CHUNKB, 1024>>>(0);
    k1_score<<<K1_GRID, 256>>>(x, 1);
    k_select<<<CHUNKB, 1024>>>(1);
    k_mask<<<M_GRID, 256>>>((const float4*)x, (float4*)out, 0);
    k1_score<<<K1_GRID, 256>>>(x, 2);
    k_select<<<CHUNKB, 1024>>>(2);
    k_mask<<<M_GRID, 256>>>((const float4*)x, (float4*)out, 1);
    k1_score<<<K1_GRID, 256>>>(x, 3);
    k_select<<<CHUNKB, 1024>>>(3);
    k_mask<<<M_GRID, 256>>>((const float4*)x, (float4*)out, 2);
    k_mask<<<M_GRID, 256>>>((const float4*)x, (float4*)out, 3);
}

// round 14
// speedup vs baseline: 2.0151x; 1.4219x over previous
#include <cuda_runtime.h>
#include <cuda_bf16.h>
#include <math.h>

// Problem constants (fixed by reference setup_inputs)
#define BB 8
#define TT 16
#define CC 64
#define NN 4096          // H*W
#define KSEL 2048        // keep_k = N*(1-0.5)

#define CHUNKB 4         // batches per chunk (67 MB < L2)
#define NCHUNK (BB / CHUNKB)
#define CGROUPS 4        // c-groups combined in-block
#define CPER 16          // channels per group
#define FULL 0xffffffffu

// Scratch (device globals — no allocation allowed)
__device__ float g_sq[BB * TT * NN];             // sqrt(sum_c x^2) per (b,t,n), 2 MB
__device__ unsigned g_maskbits[BB * (NN / 32)];  // 1 bit per (b,n)

// ---------------------------------------------------------------------------
// K1 (verified form): chunk scoring with in-block c-group combine.
// 4096 blocks x 256 threads per chunk; warp = 32 consecutive n at fixed cg.
// ---------------------------------------------------------------------------
__global__ void __launch_bounds__(256) k1_score(const float* __restrict__ x,
                                                int chunk) {
    __shared__ float s_part[CGROUPS * 64];

    const int tid = threadIdx.x;
    const int cg  = tid >> 6;                  // 0..3
    const int nl  = tid & 63;                  // 0..63
    const int btl = blockIdx.x >> 6;           // 0..63
    const int nb  = blockIdx.x & 63;           // 0..63
    const int bt  = chunk * (CHUNKB * TT) + btl;
    const int n   = nb * 64 + nl;

    const float* p = x + (size_t)bt * CC * NN + (size_t)(cg * CPER) * NN + n;
    float acc = 0.0f;
#pragma unroll
    for (int c = 0; c < CPER; ++c) {
        float v = p[(size_t)c * NN];
        acc += v * v;
    }
    s_part[cg * 64 + nl] = acc;
    __syncthreads();

    if (tid < 64) {
        float total = s_part[tid] + s_part[64 + tid]
                    + s_part[128 + tid] + s_part[192 + tid];
        g_sq[(size_t)bt * NN + nb * 64 + tid] = sqrtf(total);
    }
}

// ---------------------------------------------------------------------------
// S: per-batch exact top-K -> mask bits via HISTOGRAM radix-256.
// 1024 threads, 4 scores each. Rounds over 8-bit digit groups starting at the
// highest varying bit; round 1 does the only heavy histogram (4096 smem
// atomics spread over many bins); later rounds touch ~16 survivors.
// Exact threshold + verified lowest-index tie tail (same semantics as R4-R13).
// ---------------------------------------------------------------------------
__global__ void __launch_bounds__(1024, 1) k_select(int chunk) {
    __shared__ int s_hist[256];
    __shared__ int s_suf[256];
    __shared__ int s_wtot[8];
    __shared__ unsigned s_or[32], s_and[32];
    __shared__ unsigned s_mask[NN / 32];
    __shared__ int s_scan[32];

    const int b    = chunk * CHUNKB + blockIdx.x;
    const int j    = threadIdx.x;              // 0..1023
    const int lane = j & 31;
    const int wid  = j >> 5;

    // --- scores: 4 per thread, sequential over t (verified order) ---
    const float4* part = (const float4*)g_sq;
    float s0 = 0.f, s1 = 0.f, s2 = 0.f, s3 = 0.f;
#pragma unroll
    for (int t = 0; t < TT; ++t) {
        float4 f = part[(size_t)(b * TT + t) * (NN / 4) + j];
        s0 += f.x; s1 += f.y; s2 += f.z; s3 += f.w;
    }
    const float inv = 1.0f / (float)TT;
    unsigned u0 = __float_as_uint(s0 * inv);
    unsigned u1 = __float_as_uint(s1 * inv);
    unsigned u2 = __float_as_uint(s2 * inv);
    unsigned u3 = __float_as_uint(s3 * inv);

    if (j < NN / 32) s_mask[j] = 0u;

    // --- block OR / AND: common-prefix detection ---
    {
        unsigned ow = __reduce_or_sync(FULL, u0 | u1 | u2 | u3);
        unsigned aw = __reduce_and_sync(FULL, u0 & u1 & u2 & u3);
        if (lane == 0) { s_or[wid] = ow; s_and[wid] = aw; }
    }
    __syncthreads();
    const unsigned orv  = __reduce_or_sync(FULL, s_or[lane]);
    const unsigned andv = __reduce_and_sync(FULL, s_and[lane]);
    const unsigned diff = orv ^ andv;

    // --- histogram radix-256 select ---
    // det = lowest determined bit (bits >= det of thr are fixed in `hi`)
    const int hb = diff ? (31 - __clz((int)diff)) : 0;
    int shift = (hb >= 7) ? (hb - 7) : 0;      // round 1 covers hb..hb-7
    int det   = shift + 8;                      // may be >= 32 (=> all active)
    unsigned hi = (det < 32) ? (andv & ~((1u << det) - 1u)) : 0u;
    int G = 0;                                  // count(u > current prefix)

    for (;;) {
        if (j < 256) s_hist[j] = 0;
        __syncthreads();

        // histogram active elements (prefix bits >= det match hi)
        if (det >= 32 || ((u0 ^ hi) >> det) == 0u)
            atomicAdd(&s_hist[(u0 >> shift) & 0xFF], 1);
        if (det >= 32 || ((u1 ^ hi) >> det) == 0u)
            atomicAdd(&s_hist[(u1 >> shift) & 0xFF], 1);
        if (det >= 32 || ((u2 ^ hi) >> det) == 0u)
            atomicAdd(&s_hist[(u2 >> shift) & 0xFF], 1);
        if (det >= 32 || ((u3 ^ hi) >> det) == 0u)
            atomicAdd(&s_hist[(u3 >> shift) & 0xFF], 1);
        __syncthreads();

        // suffix sums S_j = sum_{k>=j} hist[k] (warp scan + cross-warp carry)
        int h = (j < 256) ? s_hist[j] : 0;
        int v = h;
#pragma unroll
        for (int d2 = 1; d2 < 32; d2 <<= 1) {
            int t = __shfl_down_sync(FULL, v, d2);
            if (lane + d2 < 32) v += t;
        }
        if (j < 256 && lane == 0) s_wtot[wid] = v;
        __syncthreads();
        int fj = 0;
        if (j < 256) {
            int carry = 0;
#pragma unroll
            for (int w2 = 1; w2 < 8; ++w2)
                if (w2 > wid) carry += s_wtot[w2];
            int Sj = v + carry;
            s_suf[j] = Sj;
            fj = (G + Sj >= KSEL) ? 1 : 0;
        }
        // d = largest feasible digit = (#feasible) - 1 (S_j monotone in j)
        int cnt = __syncthreads_count(fj);
        int d = cnt - 1;
        G += (d < 255) ? s_suf[d + 1] : 0;      // elements strictly above digit d
        hi |= ((unsigned)d) << shift;
        det = shift;
        if (shift == 0) break;
        shift = (shift >= 8) ? (shift - 8) : 0; // overlap rounds OK: active
        __syncthreads();                        // check uses det, not shift+8
    }

    const unsigned thr = hi;                    // exact threshold value
    const int need = KSEL - G;                  // ties to admit, lowest index first

    // --- exclusive scan over threads of per-thread equal-count (verified) ---
    int e = (u0 == thr) + (u1 == thr) + (u2 == thr) + (u3 == thr);
    int v2 = e;
#pragma unroll
    for (int d = 1; d < 32; d <<= 1) {
        int t = __shfl_up_sync(FULL, v2, d);
        if (lane >= d) v2 += t;
    }
    if (lane == 31) s_scan[wid] = v2;
    __syncthreads();
    if (wid == 0) {
        int w = s_scan[lane];
#pragma unroll
        for (int d = 1; d < 32; d <<= 1) {
            int t = __shfl_up_sync(FULL, w, d);
            if (lane >= d) w += t;
        }
        s_scan[lane] = w;
    }
    __syncthreads();
    int excl = v2 - e + (wid ? s_scan[wid - 1] : 0);

    // --- mask nibble for n = 4j..4j+3 ---
    unsigned nib = 0;
    int r = excl;
    unsigned uu[4] = {u0, u1, u2, u3};
#pragma unroll
    for (int i = 0; i < 4; ++i) {
        if (uu[i] > thr) {
            nib |= 1u << i;
        } else if (uu[i] == thr) {
            if (r < need) nib |= 1u << i;
            ++r;
        }
    }
    atomicOr(&s_mask[j >> 3], nib << ((j & 7) * 4));
    __syncthreads();
    if (j < NN / 32) g_maskbits[b * (NN / 32) + j] = s_mask[j];
}

// ---------------------------------------------------------------------------
// M: masked copy for one chunk (verified). Reads hit x[chunk]'s L2 residue:
// only S (tiny) runs between K1(c) and M(c), and 67 MB < L2 capacity.
// ---------------------------------------------------------------------------
__global__ void __launch_bounds__(256) k_mask(const float4* __restrict__ x4,
                                              float4* __restrict__ o4,
                                              int chunk) {
    unsigned i = (unsigned)chunk * (CHUNKB * TT * CC * (NN / 4))
               + blockIdx.x * 256 + threadIdx.x;
    int n4 = i & ((NN / 4) - 1);
    int b  = i >> 20;                        // 2^20 float4 per batch
    int n  = n4 << 2;
    unsigned mword = g_maskbits[(b << 7) + (n >> 5)];
    unsigned bits  = mword >> (n & 31);
    float4 v = __ldcs(&x4[(size_t)i]);
    v.x = (bits & 1u) ? v.x : 0.0f;
    v.y = (bits & 2u) ? v.y : 0.0f;
    v.z = (bits & 4u) ? v.z : 0.0f;
    v.w = (bits & 8u) ? v.w : 0.0f;
    __stcs(&o4[(size_t)i], v);
}

// ---------------------------------------------------------------------------
extern "C" void kernel_launch(void* const* d_in, const int* in_sizes, int n_in,
                              void* d_out, int out_size) {
    const float* x = (const float*)d_in[0];
    float* out = (float*)d_out;

    const int K1_GRID = CHUNKB * TT * 64;                   // 4096 blocks
    const int M_GRID  = CHUNKB * TT * CC * NN / 4 / 256;    // 16384 blocks

    // Per chunk: score (x -> L2), select (tiny), masked copy (L2-hot reads).
    k1_score<<<K1_GRID, 256>>>(x, 0);
    k_select<<<CHUNKB, 1024>>>(0);
    k_mask<<<M_GRID, 256>>>((const float4*)x, (float4*)out, 0);
    k1_score<<<K1_GRID, 256>>>(x, 1);
    k_select<<<CHUNKB, 1024>>>(1);
    k_mask<<<M_GRID, 256>>>((const float4*)x, (float4*)out, 1);
}